// round 12
// baseline (speedup 1.0000x reference)
#include <cuda_runtime.h>
#include <cuda_fp16.h>
#include <math.h>

#define N_NODES 30000
#define N_EDGES 480000

// ---------------- scratch (static device globals; no allocation) ----------------
__device__ float g_kqv[N_NODES * 768];     // kp|q|vp packed fp32 (q cols used by attn)
__device__ __half g_kph[N_NODES * 256];    // fp16 kp for edge gather
__device__ __half g_vph[N_NODES * 256];    // fp16 vp for edge gather
__device__ float g_agg[N_NODES * 256];     // normalized attention output
__device__ float g_tmp[N_NODES * 256];     // out1 pre-BN
__device__ float g_bnsum[256];
__device__ float g_bnsq [256];
__device__ float g_w1p[512 * 768];         // combined L1 weights
__device__ float g_b1p[768];
__device__ float g_w2p[256 * 768];         // combined L2 weights
__device__ float g_b2p[768];
__device__ int   g_count [N_NODES];        // CSR build
__device__ int   g_off   [N_NODES + 1];
__device__ int   g_cursor[N_NODES];
__device__ int   g_esrc  [N_EDGES];        // src ids sorted by dst

// ---------------- helpers ----------------
__device__ __forceinline__ float gelu_exact(float v) {
    return 0.5f * v * (1.0f + erff(v * 0.70710678118654752f));
}
__device__ __forceinline__ float bn_relu(float v, int col,
                                         const float* __restrict__ bnsum,
                                         const float* __restrict__ bnsq,
                                         const float* __restrict__ gamma,
                                         const float* __restrict__ beta) {
    const float inv_n = 1.0f / (float)N_NODES;
    float mu = bnsum[col] * inv_n;
    float var = bnsq[col] * inv_n - mu * mu;
    float r = (v - mu) * rsqrtf(var + 1e-5f) * gamma[col] + beta[col];
    return fmaxf(r, 0.f);
}
__device__ __forceinline__ unsigned pack_h2(float a, float b) {
    __half2 h = __floats2half2_rn(a, b);
    return *(unsigned*)&h;
}
// m16n8k16 fp16 mma, fp32 accumulate
__device__ __forceinline__ void mma_f16(float* d, const unsigned* a, const unsigned* b) {
    asm volatile("mma.sync.aligned.m16n8k16.row.col.f32.f16.f16.f32 "
                 "{%0,%1,%2,%3}, {%4,%5,%6,%7}, {%8,%9}, {%0,%1,%2,%3};"
                 : "+f"(d[0]), "+f"(d[1]), "+f"(d[2]), "+f"(d[3])
                 : "r"(a[0]), "r"(a[1]), "r"(a[2]), "r"(a[3]), "r"(b[0]), "r"(b[1]));
}
__device__ __forceinline__ float dot8h(float4 q1, float4 q2, uint4 ku) {
    const __half2* kh = (const __half2*)&ku;
    float2 a = __half22float2(kh[0]);
    float2 b = __half22float2(kh[1]);
    float2 c = __half22float2(kh[2]);
    float2 d = __half22float2(kh[3]);
    return q1.x * a.x + q1.y * a.y + q1.z * b.x + q1.w * b.y
         + q2.x * c.x + q2.y * c.y + q2.z * d.x + q2.w * d.y;
}

// ---------------- weight combine: W' = [Wk@Krel_bd | Wq | Wv@Vrel_bd] ----------------
__global__ void combine_kernel(const float* __restrict__ W, const float* __restrict__ b,
                               const float* __restrict__ krel, const float* __restrict__ vrel,
                               float* __restrict__ Wp, float* __restrict__ bp,
                               int IN, int D) {
    int idx = blockIdx.x * blockDim.x + threadIdx.x;
    if (idx >= (IN + 1) * 768) return;
    int row = idx / 768, c = idx % 768;
    const float* src = (row < IN) ? (W + (size_t)row * 768) : b;
    float val;
    if (c >= 256 && c < 512) {
        val = src[c];
    } else {
        const float* rel = (c < 256) ? krel : vrel;
        int cc = (c < 256) ? c : (c - 512);
        int base = (c < 256) ? 0 : 512;
        int h = cc / D, e = cc % D;
        float s = 0.f;
        for (int d = 0; d < D; d++)
            s += src[base + h * D + d] * rel[(h * D + d) * D + e];
        val = s;
    }
    if (row < IN) Wp[(size_t)row * 768 + c] = val;
    else          bp[c] = val;
}

// ---------------- CSR build ----------------
__global__ void zero_init_kernel(int* __restrict__ count, float* __restrict__ bnsum,
                                 float* __restrict__ bnsq) {
    int i = blockIdx.x * blockDim.x + threadIdx.x;
    if (i < N_NODES) count[i] = 0;
    if (i < 256) { bnsum[i] = 0.f; bnsq[i] = 0.f; }
}
__global__ void hist_kernel(const int* __restrict__ dst, int* __restrict__ count) {
    int i = blockIdx.x * blockDim.x + threadIdx.x;
    if (i < N_EDGES) atomicAdd(&count[dst[i]], 1);
}
__global__ void scan_kernel(const int* __restrict__ count, int* __restrict__ off,
                            int* __restrict__ cursor) {
    __shared__ int part[1024];
    const int tid = threadIdx.x;
    const int chunk = (N_NODES + 1023) / 1024;
    const int start = tid * chunk;
    int s = 0;
    for (int i = 0; i < chunk; i++) {
        int idx = start + i;
        if (idx < N_NODES) s += count[idx];
    }
    part[tid] = s;
    __syncthreads();
    for (int o = 1; o < 1024; o <<= 1) {
        int v = (tid >= o) ? part[tid - o] : 0;
        __syncthreads();
        part[tid] += v;
        __syncthreads();
    }
    int run = (tid > 0) ? part[tid - 1] : 0;
    for (int i = 0; i < chunk; i++) {
        int idx = start + i;
        if (idx < N_NODES) {
            off[idx] = run;
            cursor[idx] = run;
            run += count[idx];
        }
    }
    if (tid == 0) off[N_NODES] = part[1023];
}
__global__ void scatter_kernel(const int* __restrict__ src, const int* __restrict__ dst,
                               int* __restrict__ cursor, int* __restrict__ esrc) {
    int i = blockIdx.x * blockDim.x + threadIdx.x;
    if (i >= N_EDGES) return;
    int p = atomicAdd(&cursor[dst[i]], 1);
    esrc[p] = src[i];
}

// ---------------- fused attention: warp per dst, 2-edge online softmax, fp16 k/v ----------------
template <int H>
__global__ void attn_kernel(const float* __restrict__ q,
                            const __half* __restrict__ kph, const __half* __restrict__ vph,
                            const int* __restrict__ off, const int* __restrict__ esrc,
                            const float* __restrict__ p_rel,
                            float* __restrict__ agg, float inv_sqrt_d) {
    int w = blockIdx.x * (blockDim.x >> 5) + (threadIdx.x >> 5);
    if (w >= N_NODES) return;
    const int lane = threadIdx.x & 31;
    const int G = 32 / H;
    const int h = lane / G;
    const float pr = p_rel[h] * inv_sqrt_d;

    const float4* qv = (const float4*)(q + (size_t)w * 768);
    float4 q1 = qv[lane * 2], q2 = qv[lane * 2 + 1];

    int beg = off[w], end = off[w + 1];
    float m = -INFINITY, denom = 0.f;
    float a0 = 0.f, a1 = 0.f, a2 = 0.f, a3 = 0.f;
    float a4 = 0.f, a5 = 0.f, a6 = 0.f, a7 = 0.f;

    int e = beg;
    for (; e + 1 < end; e += 2) {
        int s0 = esrc[e], s1 = esrc[e + 1];
        uint4 ku0 = ((const uint4*)(kph + (size_t)s0 * 256))[lane];
        uint4 ku1 = ((const uint4*)(kph + (size_t)s1 * 256))[lane];
        uint4 vu0 = ((const uint4*)(vph + (size_t)s0 * 256))[lane];
        uint4 vu1 = ((const uint4*)(vph + (size_t)s1 * 256))[lane];
        float d0 = dot8h(q1, q2, ku0);
        float d1 = dot8h(q1, q2, ku1);
        #pragma unroll
        for (int o = G / 2; o > 0; o >>= 1) {
            d0 += __shfl_xor_sync(0xffffffffu, d0, o);
            d1 += __shfl_xor_sync(0xffffffffu, d1, o);
        }
        float l0 = d0 * pr, l1 = d1 * pr;
        float mm = fmaxf(m, fmaxf(l0, l1));
        float c  = expf(m - mm);
        float e0 = expf(l0 - mm);
        float e1 = expf(l1 - mm);
        m = mm;
        denom = denom * c + e0 + e1;
        const __half2* v0h = (const __half2*)&vu0;
        const __half2* v1h = (const __half2*)&vu1;
        float2 p0 = __half22float2(v0h[0]), p1 = __half22float2(v0h[1]);
        float2 p2 = __half22float2(v0h[2]), p3 = __half22float2(v0h[3]);
        float2 r0 = __half22float2(v1h[0]), r1 = __half22float2(v1h[1]);
        float2 r2 = __half22float2(v1h[2]), r3 = __half22float2(v1h[3]);
        a0 = a0 * c + e0 * p0.x + e1 * r0.x;
        a1 = a1 * c + e0 * p0.y + e1 * r0.y;
        a2 = a2 * c + e0 * p1.x + e1 * r1.x;
        a3 = a3 * c + e0 * p1.y + e1 * r1.y;
        a4 = a4 * c + e0 * p2.x + e1 * r2.x;
        a5 = a5 * c + e0 * p2.y + e1 * r2.y;
        a6 = a6 * c + e0 * p3.x + e1 * r3.x;
        a7 = a7 * c + e0 * p3.y + e1 * r3.y;
    }
    if (e < end) {      // tail edge
        int s0 = esrc[e];
        uint4 ku0 = ((const uint4*)(kph + (size_t)s0 * 256))[lane];
        uint4 vu0 = ((const uint4*)(vph + (size_t)s0 * 256))[lane];
        float d0 = dot8h(q1, q2, ku0);
        #pragma unroll
        for (int o = G / 2; o > 0; o >>= 1)
            d0 += __shfl_xor_sync(0xffffffffu, d0, o);
        float l0 = d0 * pr;
        float mm = fmaxf(m, l0);
        float c  = expf(m - mm);
        float e0 = expf(l0 - mm);
        m = mm;
        denom = denom * c + e0;
        const __half2* v0h = (const __half2*)&vu0;
        float2 p0 = __half22float2(v0h[0]), p1 = __half22float2(v0h[1]);
        float2 p2 = __half22float2(v0h[2]), p3 = __half22float2(v0h[3]);
        a0 = a0 * c + e0 * p0.x; a1 = a1 * c + e0 * p0.y;
        a2 = a2 * c + e0 * p1.x; a3 = a3 * c + e0 * p1.y;
        a4 = a4 * c + e0 * p2.x; a5 = a5 * c + e0 * p2.y;
        a6 = a6 * c + e0 * p3.x; a7 = a7 * c + e0 * p3.y;
    }
    float invd = 1.0f / (denom + 1e-16f);
    float4* o4 = (float4*)(agg + (size_t)w * 256);
    o4[lane * 2]     = make_float4(a0 * invd, a1 * invd, a2 * invd, a3 * invd);
    o4[lane * 2 + 1] = make_float4(a4 * invd, a5 * invd, a6 * invd, a7 * invd);
}

// ---------------- fp16 GEMM: 128x128x32 tiles, m16n8k16 mma, double-buffered ----------------
// ACT: 0 = identity, 1 = gelu(A), 3 = BN+ReLU(A) via stats
// SKIP: 0 = none, 2 = blend with relu(bn(hres)) recomputed in epilogue
// PACKH: 1 = write fp16 k (cols<256) / v (cols>=512); fp32 store only q cols
// Layouts: A smem row-major fp16 [2][128][40]; B smem k-paired __half2 [2][16][128].
#define ASH(b,r,c) sA[(size_t)(b)*128*40 + (r)*40 + (c)]
#define BSH(b,kp,n) sB[(size_t)(b)*16*128 + (kp)*128 + (n)]
#define GEMM_SMEM (2*128*40*2 + 2*16*128*4)

template <int ACT, int SKIP, int PACKH>
__global__ __launch_bounds__(256)
void gemm_f16(const float* __restrict__ A, const float* __restrict__ B,
              const float* __restrict__ bias, float* __restrict__ C,
              int M, int K, int N, int lda, int ldb, int ldc,
              const float* __restrict__ skipv, const float* __restrict__ hres,
              const float* __restrict__ bnsum, const float* __restrict__ bnsq,
              const float* __restrict__ gamma, const float* __restrict__ beta,
              __half* __restrict__ kph, __half* __restrict__ vph) {
    extern __shared__ unsigned char smem_raw[];
    __half* sA = (__half*)smem_raw;                            // [2][128][40]
    unsigned* sB = (unsigned*)(smem_raw + 2 * 128 * 40 * 2);   // [2][16][128] half2

    const int bm = blockIdx.y * 128;
    const int bn = blockIdx.x * 128;
    const int tid = threadIdx.x;        // 256
    const int wid = tid >> 5, lane = tid & 31;
    const int wm = (wid >> 1) * 32;
    const int wn = (wid & 1) * 64;
    const int gq = lane >> 2;           // 0..7
    const int qc = lane & 3;            // 0..3

    // A loader: row = tid>>3 (+32*l), k-quad = (tid&7)*4
    const int arow = tid >> 3;
    const int akq  = (tid & 7) * 4;
    // B loader: k-pair = tid>>4 (0..15), n-quad = (tid&15)*4 (+64 second pass)
    const int bkp = tid >> 4;
    const int bn4 = (tid & 15) * 4;

    float acc[2][8][4] = {};
    const float4 z4 = make_float4(0.f, 0.f, 0.f, 0.f);

    // ---- A activation + fp16 store helper (lambda-free, inline) ----
    // ---- prologue: load stage 0 ----
    #pragma unroll
    for (int l = 0; l < 4; l++) {
        int row = arow + l * 32;
        int gm = bm + row;
        float4 v = (gm < M) ? *(const float4*)(A + (size_t)gm * lda + akq) : z4;
        if (ACT == 1) {
            v.x = gelu_exact(v.x); v.y = gelu_exact(v.y);
            v.z = gelu_exact(v.z); v.w = gelu_exact(v.w);
        } else if (ACT == 3) {
            v.x = bn_relu(v.x, akq + 0, bnsum, bnsq, gamma, beta);
            v.y = bn_relu(v.y, akq + 1, bnsum, bnsq, gamma, beta);
            v.z = bn_relu(v.z, akq + 2, bnsum, bnsq, gamma, beta);
            v.w = bn_relu(v.w, akq + 3, bnsum, bnsq, gamma, beta);
        }
        *(uint2*)&ASH(0, row, akq) = make_uint2(pack_h2(v.x, v.y), pack_h2(v.z, v.w));
    }
    #pragma unroll
    for (int l = 0; l < 2; l++) {
        int n4 = bn4 + l * 64;
        float4 r0 = *(const float4*)(B + (size_t)(2 * bkp)     * ldb + bn + n4);
        float4 r1 = *(const float4*)(B + (size_t)(2 * bkp + 1) * ldb + bn + n4);
        *(uint4*)&BSH(0, bkp, n4) = make_uint4(pack_h2(r0.x, r1.x), pack_h2(r0.y, r1.y),
                                               pack_h2(r0.z, r1.z), pack_h2(r0.w, r1.w));
    }
    __syncthreads();

    for (int k0 = 0; k0 < K; k0 += 32) {
        const int cur = (k0 >> 5) & 1, nxt = cur ^ 1;
        const int kn = k0 + 32;
        const bool have_next = kn < K;

        // ---- issue next-stage LDGs ----
        float4 ra[4], rb0[2], rb1[2];
        if (have_next) {
            #pragma unroll
            for (int l = 0; l < 4; l++) {
                int gm = bm + arow + l * 32;
                ra[l] = (gm < M) ? *(const float4*)(A + (size_t)gm * lda + kn + akq) : z4;
            }
            #pragma unroll
            for (int l = 0; l < 2; l++) {
                int n4 = bn4 + l * 64;
                rb0[l] = *(const float4*)(B + (size_t)(kn + 2 * bkp)     * ldb + bn + n4);
                rb1[l] = *(const float4*)(B + (size_t)(kn + 2 * bkp + 1) * ldb + bn + n4);
            }
        }

        // ---- 2 k16 mma steps on current buffer ----
        #pragma unroll
        for (int kb = 0; kb < 32; kb += 16) {
            unsigned af[2][4];
            #pragma unroll
            for (int mt = 0; mt < 2; mt++) {
                int r = wm + mt * 16 + gq;
                af[mt][0] = *(const unsigned*)&ASH(cur, r,     kb + 2 * qc);
                af[mt][1] = *(const unsigned*)&ASH(cur, r + 8, kb + 2 * qc);
                af[mt][2] = *(const unsigned*)&ASH(cur, r,     kb + 2 * qc + 8);
                af[mt][3] = *(const unsigned*)&ASH(cur, r + 8, kb + 2 * qc + 8);
            }
            #pragma unroll
            for (int nt = 0; nt < 8; nt++) {
                int n = wn + nt * 8 + gq;
                unsigned bf[2];
                bf[0] = BSH(cur, (kb >> 1) + qc,     n);
                bf[1] = BSH(cur, (kb >> 1) + qc + 4, n);
                mma_f16(acc[0][nt], af[0], bf);
                mma_f16(acc[1][nt], af[1], bf);
            }
        }

        // ---- store next stage ----
        if (have_next) {
            #pragma unroll
            for (int l = 0; l < 4; l++) {
                float4 v = ra[l];
                if (ACT == 1) {
                    v.x = gelu_exact(v.x); v.y = gelu_exact(v.y);
                    v.z = gelu_exact(v.z); v.w = gelu_exact(v.w);
                } else if (ACT == 3) {
                    v.x = bn_relu(v.x, kn + akq + 0, bnsum, bnsq, gamma, beta);
                    v.y = bn_relu(v.y, kn + akq + 1, bnsum, bnsq, gamma, beta);
                    v.z = bn_relu(v.z, kn + akq + 2, bnsum, bnsq, gamma, beta);
                    v.w = bn_relu(v.w, kn + akq + 3, bnsum, bnsq, gamma, beta);
                }
                *(uint2*)&ASH(nxt, arow + l * 32, akq) =
                    make_uint2(pack_h2(v.x, v.y), pack_h2(v.z, v.w));
            }
            #pragma unroll
            for (int l = 0; l < 2; l++) {
                int n4 = bn4 + l * 64;
                *(uint4*)&BSH(nxt, bkp, n4) =
                    make_uint4(pack_h2(rb0[l].x, rb1[l].x), pack_h2(rb0[l].y, rb1[l].y),
                               pack_h2(rb0[l].z, rb1[l].z), pack_h2(rb0[l].w, rb1[l].w));
            }
        }
        __syncthreads();
    }

    // ---- epilogue (C fragment layout identical to m16n8k8) ----
    float s = 1.f, s1 = 0.f;
    if (SKIP == 2) {
        s = 1.0f / (1.0f + expf(-skipv[0]));
        s1 = 1.0f - s;
    }
    #pragma unroll
    for (int mt = 0; mt < 2; mt++) {
        #pragma unroll
        for (int half = 0; half < 2; half++) {
            int gm = bm + wm + mt * 16 + half * 8 + gq;
            if (gm >= M) continue;
            #pragma unroll
            for (int nt = 0; nt < 8; nt++) {
                int gn = bn + wn + nt * 8 + qc * 2;
                float v0 = acc[mt][nt][half * 2 + 0];
                float v1 = acc[mt][nt][half * 2 + 1];
                if (bias) { v0 += bias[gn]; v1 += bias[gn + 1]; }
                if (SKIP == 2) {
                    const float* hb = hres + (size_t)gm * ldc + gn;
                    float h0 = bn_relu(hb[0], gn,     bnsum, bnsq, gamma, beta);
                    float h1 = bn_relu(hb[1], gn + 1, bnsum, bnsq, gamma, beta);
                    v0 = s * v0 + s1 * h0;
                    v1 = s * v1 + s1 * h1;
                }
                if (PACKH) {
                    if (gn < 256) {
                        *(__half2*)(kph + (size_t)gm * 256 + gn) = __floats2half2_rn(v0, v1);
                    } else if (gn >= 512) {
                        *(__half2*)(vph + (size_t)gm * 256 + gn - 512) = __floats2half2_rn(v0, v1);
                    } else {
                        *(float2*)(C + (size_t)gm * ldc + gn) = make_float2(v0, v1);
                    }
                } else {
                    *(float2*)(C + (size_t)gm * ldc + gn) = make_float2(v0, v1);
                }
            }
        }
    }
}

// ---------------- BN stats ----------------
__global__ void bn_stats_kernel(const float* __restrict__ x, float* __restrict__ sum,
                                float* __restrict__ sumsq, int n) {
    int col = threadIdx.x;
    float s = 0.f, s2 = 0.f;
    for (int r = blockIdx.x; r < n; r += gridDim.x) {
        float v = x[(size_t)r * 256 + col];
        s += v; s2 += v * v;
    }
    atomicAdd(&sum[col], s);
    atomicAdd(&sumsq[col], s2);
}

// ---------------- host orchestration ----------------
extern "C" void kernel_launch(void* const* d_in, const int* in_sizes, int n_in,
                              void* d_out, int out_size) {
    const float* x       = (const float*)d_in[0];
    const int*   ei      = (const int*)  d_in[1];
    const float* w_kqv1  = (const float*)d_in[2];
    const float* b_kqv1  = (const float*)d_in[3];
    const float* k_rel1  = (const float*)d_in[4];
    const float* v_rel1  = (const float*)d_in[5];
    const float* p_rel1  = (const float*)d_in[6];
    const float* w_out1  = (const float*)d_in[7];
    const float* b_out1  = (const float*)d_in[8];
    const float* bn_gamma = (const float*)d_in[10];
    const float* bn_beta  = (const float*)d_in[11];
    const float* w_kqv2  = (const float*)d_in[12];
    const float* b_kqv2  = (const float*)d_in[13];
    const float* k_rel2  = (const float*)d_in[14];
    const float* v_rel2  = (const float*)d_in[15];
    const float* p_rel2  = (const float*)d_in[16];
    const float* w_out2  = (const float*)d_in[17];
    const float* b_out2  = (const float*)d_in[18];
    const float* skip2   = (const float*)d_in[19];

    const int* src = ei;
    const int* dst = ei + N_EDGES;
    float* outp = (float*)d_out;

    float *kqv, *agg, *tmp, *bnsum, *bnsq;
    float *w1p, *b1p, *w2p, *b2p;
    __half *kph, *vph;
    int *count, *off, *cursor, *esrc;
    cudaGetSymbolAddress((void**)&kqv,    g_kqv);
    cudaGetSymbolAddress((void**)&kph,    g_kph);
    cudaGetSymbolAddress((void**)&vph,    g_vph);
    cudaGetSymbolAddress((void**)&agg,    g_agg);
    cudaGetSymbolAddress((void**)&tmp,    g_tmp);
    cudaGetSymbolAddress((void**)&bnsum,  g_bnsum);
    cudaGetSymbolAddress((void**)&bnsq,   g_bnsq);
    cudaGetSymbolAddress((void**)&w1p,    g_w1p);
    cudaGetSymbolAddress((void**)&b1p,    g_b1p);
    cudaGetSymbolAddress((void**)&w2p,    g_w2p);
    cudaGetSymbolAddress((void**)&b2p,    g_b2p);
    cudaGetSymbolAddress((void**)&count,  g_count);
    cudaGetSymbolAddress((void**)&off,    g_off);
    cudaGetSymbolAddress((void**)&cursor, g_cursor);
    cudaGetSymbolAddress((void**)&esrc,   g_esrc);

    cudaFuncSetAttribute(gemm_f16<0,0,1>, cudaFuncAttributeMaxDynamicSharedMemorySize, GEMM_SMEM);
    cudaFuncSetAttribute(gemm_f16<3,0,1>, cudaFuncAttributeMaxDynamicSharedMemorySize, GEMM_SMEM);
    cudaFuncSetAttribute(gemm_f16<1,0,0>, cudaFuncAttributeMaxDynamicSharedMemorySize, GEMM_SMEM);
    cudaFuncSetAttribute(gemm_f16<1,2,0>, cudaFuncAttributeMaxDynamicSharedMemorySize, GEMM_SMEM);

    const int MT128 = (N_NODES + 127) / 128;   // 235
    const int ATTN_BLOCKS = (N_NODES + 7) / 8;

    // ---- weight prep ----
    combine_kernel<<<((512 + 1) * 768 + 255) / 256, 256>>>(w_kqv1, b_kqv1, k_rel1, v_rel1,
                                                           w1p, b1p, 512, 64);
    combine_kernel<<<((256 + 1) * 768 + 255) / 256, 256>>>(w_kqv2, b_kqv2, k_rel2, v_rel2,
                                                           w2p, b2p, 256, 256);

    // ---- CSR build ----
    zero_init_kernel<<<(N_NODES + 255) / 256, 256>>>(count, bnsum, bnsq);
    hist_kernel<<<(N_EDGES + 255) / 256, 256>>>(dst, count);
    scan_kernel<<<1, 1024>>>(count, off, cursor);
    scatter_kernel<<<(N_EDGES + 255) / 256, 256>>>(src, dst, cursor, esrc);

    // ================= Layer 1 (heads=4, d=64) =================
    gemm_f16<0,0,1><<<dim3(768 / 128, MT128), 256, GEMM_SMEM>>>(x, w1p, b1p, kqv,
        N_NODES, 512, 768, 512, 768, 768, nullptr, nullptr,
        nullptr, nullptr, nullptr, nullptr, kph, vph);
    attn_kernel<4><<<ATTN_BLOCKS, 256>>>(kqv + 256, kph, vph, off, esrc, p_rel1,
                                         agg, 0.125f);
    gemm_f16<1,0,0><<<dim3(256 / 128, MT128), 256, GEMM_SMEM>>>(agg, w_out1, b_out1, tmp,
        N_NODES, 256, 256, 256, 256, 256, nullptr, nullptr,
        nullptr, nullptr, nullptr, nullptr, nullptr, nullptr);
    bn_stats_kernel<<<256, 256>>>(tmp, bnsum, bnsq, N_NODES);

    // ================= Layer 2 (heads=1, d=256) =================
    gemm_f16<3,0,1><<<dim3(768 / 128, MT128), 256, GEMM_SMEM>>>(tmp, w2p, b2p, kqv,
        N_NODES, 256, 768, 256, 768, 768, nullptr, nullptr,
        bnsum, bnsq, bn_gamma, bn_beta, kph, vph);
    attn_kernel<1><<<ATTN_BLOCKS, 256>>>(kqv + 256, kph, vph, off, esrc, p_rel2,
                                         agg, 0.0625f);
    gemm_f16<1,2,0><<<dim3(256 / 128, MT128), 256, GEMM_SMEM>>>(agg, w_out2, b_out2, outp,
        N_NODES, 256, 256, 256, 256, 256, skip2, tmp,
        bnsum, bnsq, bn_gamma, bn_beta, nullptr, nullptr);

    (void)in_sizes; (void)n_in; (void)out_size;
}

// round 14
// speedup vs baseline: 1.7173x; 1.7173x over previous
#include <cuda_runtime.h>
#include <cuda_fp16.h>
#include <math.h>

#define N_NODES 30000
#define N_EDGES 480000

// ---------------- scratch (static device globals; no allocation) ----------------
__device__ float g_kqv[N_NODES * 768];     // kp|q|vp packed fp32 (q cols used by attn)
__device__ __half g_kph[N_NODES * 256];    // fp16 kp for edge gather
__device__ __half g_vph[N_NODES * 256];    // fp16 vp for edge gather
__device__ float g_agg[N_NODES * 256];     // normalized attention output
__device__ float g_tmp[N_NODES * 256];     // out1 pre-BN
__device__ float g_bnsum[256];
__device__ float g_bnsq [256];
__device__ float g_w1p[512 * 768];         // combined L1 weights
__device__ float g_b1p[768];
__device__ float g_w2p[256 * 768];         // combined L2 weights
__device__ float g_b2p[768];
__device__ int   g_count [N_NODES];        // CSR build
__device__ int   g_off   [N_NODES + 1];
__device__ int   g_cursor[N_NODES];
__device__ int   g_esrc  [N_EDGES];        // src ids sorted by dst

// ---------------- helpers ----------------
__device__ __forceinline__ float gelu_exact(float v) {
    return 0.5f * v * (1.0f + erff(v * 0.70710678118654752f));
}
__device__ __forceinline__ float bn_relu(float v, int col,
                                         const float* __restrict__ bnsum,
                                         const float* __restrict__ bnsq,
                                         const float* __restrict__ gamma,
                                         const float* __restrict__ beta) {
    const float inv_n = 1.0f / (float)N_NODES;
    float mu = bnsum[col] * inv_n;
    float var = bnsq[col] * inv_n - mu * mu;
    float r = (v - mu) * rsqrtf(var + 1e-5f) * gamma[col] + beta[col];
    return fmaxf(r, 0.f);
}
__device__ __forceinline__ unsigned pack_h2(float a, float b) {
    __half2 h = __floats2half2_rn(a, b);
    return *(unsigned*)&h;
}
// m16n8k16 fp16 mma, fp32 accumulate
__device__ __forceinline__ void mma_f16(float* d, const unsigned* a, const unsigned* b) {
    asm volatile("mma.sync.aligned.m16n8k16.row.col.f32.f16.f16.f32 "
                 "{%0,%1,%2,%3}, {%4,%5,%6,%7}, {%8,%9}, {%0,%1,%2,%3};"
                 : "+f"(d[0]), "+f"(d[1]), "+f"(d[2]), "+f"(d[3])
                 : "r"(a[0]), "r"(a[1]), "r"(a[2]), "r"(a[3]), "r"(b[0]), "r"(b[1]));
}
__device__ __forceinline__ float dot8h(float4 q1, float4 q2, uint4 ku) {
    const __half2* kh = (const __half2*)&ku;
    float2 a = __half22float2(kh[0]);
    float2 b = __half22float2(kh[1]);
    float2 c = __half22float2(kh[2]);
    float2 d = __half22float2(kh[3]);
    return q1.x * a.x + q1.y * a.y + q1.z * b.x + q1.w * b.y
         + q2.x * c.x + q2.y * c.y + q2.z * d.x + q2.w * d.y;
}

// ---------------- weight combine: W' = [Wk@Krel_bd | Wq | Wv@Vrel_bd] ----------------
__global__ void combine_kernel(const float* __restrict__ W, const float* __restrict__ b,
                               const float* __restrict__ krel, const float* __restrict__ vrel,
                               float* __restrict__ Wp, float* __restrict__ bp,
                               int IN, int D) {
    int idx = blockIdx.x * blockDim.x + threadIdx.x;
    if (idx >= (IN + 1) * 768) return;
    int row = idx / 768, c = idx % 768;
    const float* src = (row < IN) ? (W + (size_t)row * 768) : b;
    float val;
    if (c >= 256 && c < 512) {
        val = src[c];
    } else {
        const float* rel = (c < 256) ? krel : vrel;
        int cc = (c < 256) ? c : (c - 512);
        int base = (c < 256) ? 0 : 512;
        int h = cc / D, e = cc % D;
        float s = 0.f;
        for (int d = 0; d < D; d++)
            s += src[base + h * D + d] * rel[(h * D + d) * D + e];
        val = s;
    }
    if (row < IN) Wp[(size_t)row * 768 + c] = val;
    else          bp[c] = val;
}

// ---------------- CSR build ----------------
__global__ void zero_init_kernel(int* __restrict__ count, float* __restrict__ bnsum,
                                 float* __restrict__ bnsq) {
    int i = blockIdx.x * blockDim.x + threadIdx.x;
    if (i < N_NODES) count[i] = 0;
    if (i < 256) { bnsum[i] = 0.f; bnsq[i] = 0.f; }
}
__global__ void hist_kernel(const int* __restrict__ dst, int* __restrict__ count) {
    int i = blockIdx.x * blockDim.x + threadIdx.x;
    if (i < N_EDGES) atomicAdd(&count[dst[i]], 1);
}
__global__ void scan_kernel(const int* __restrict__ count, int* __restrict__ off,
                            int* __restrict__ cursor) {
    __shared__ int part[1024];
    const int tid = threadIdx.x;
    const int chunk = (N_NODES + 1023) / 1024;
    const int start = tid * chunk;
    int s = 0;
    for (int i = 0; i < chunk; i++) {
        int idx = start + i;
        if (idx < N_NODES) s += count[idx];
    }
    part[tid] = s;
    __syncthreads();
    for (int o = 1; o < 1024; o <<= 1) {
        int v = (tid >= o) ? part[tid - o] : 0;
        __syncthreads();
        part[tid] += v;
        __syncthreads();
    }
    int run = (tid > 0) ? part[tid - 1] : 0;
    for (int i = 0; i < chunk; i++) {
        int idx = start + i;
        if (idx < N_NODES) {
            off[idx] = run;
            cursor[idx] = run;
            run += count[idx];
        }
    }
    if (tid == 0) off[N_NODES] = part[1023];
}
__global__ void scatter_kernel(const int* __restrict__ src, const int* __restrict__ dst,
                               int* __restrict__ cursor, int* __restrict__ esrc) {
    int i = blockIdx.x * blockDim.x + threadIdx.x;
    if (i >= N_EDGES) return;
    int p = atomicAdd(&cursor[dst[i]], 1);
    esrc[p] = src[i];
}

// ---------------- fused attention: warp per dst, 2-edge online softmax, fp16 k/v ----------------
template <int H>
__global__ void attn_kernel(const float* __restrict__ q,
                            const __half* __restrict__ kph, const __half* __restrict__ vph,
                            const int* __restrict__ off, const int* __restrict__ esrc,
                            const float* __restrict__ p_rel,
                            float* __restrict__ agg, float inv_sqrt_d) {
    int w = blockIdx.x * (blockDim.x >> 5) + (threadIdx.x >> 5);
    if (w >= N_NODES) return;
    const int lane = threadIdx.x & 31;
    const int G = 32 / H;
    const int h = lane / G;
    const float pr = p_rel[h] * inv_sqrt_d;

    const float4* qv = (const float4*)(q + (size_t)w * 768);
    float4 q1 = qv[lane * 2], q2 = qv[lane * 2 + 1];

    int beg = off[w], end = off[w + 1];
    float m = -INFINITY, denom = 0.f;
    float a0 = 0.f, a1 = 0.f, a2 = 0.f, a3 = 0.f;
    float a4 = 0.f, a5 = 0.f, a6 = 0.f, a7 = 0.f;

    int e = beg;
    for (; e + 1 < end; e += 2) {
        int s0 = esrc[e], s1 = esrc[e + 1];
        uint4 ku0 = ((const uint4*)(kph + (size_t)s0 * 256))[lane];
        uint4 ku1 = ((const uint4*)(kph + (size_t)s1 * 256))[lane];
        uint4 vu0 = ((const uint4*)(vph + (size_t)s0 * 256))[lane];
        uint4 vu1 = ((const uint4*)(vph + (size_t)s1 * 256))[lane];
        float d0 = dot8h(q1, q2, ku0);
        float d1 = dot8h(q1, q2, ku1);
        #pragma unroll
        for (int o = G / 2; o > 0; o >>= 1) {
            d0 += __shfl_xor_sync(0xffffffffu, d0, o);
            d1 += __shfl_xor_sync(0xffffffffu, d1, o);
        }
        float l0 = d0 * pr, l1 = d1 * pr;
        float mm = fmaxf(m, fmaxf(l0, l1));
        float c  = expf(m - mm);
        float e0 = expf(l0 - mm);
        float e1 = expf(l1 - mm);
        m = mm;
        denom = denom * c + e0 + e1;
        const __half2* v0h = (const __half2*)&vu0;
        const __half2* v1h = (const __half2*)&vu1;
        float2 p0 = __half22float2(v0h[0]), p1 = __half22float2(v0h[1]);
        float2 p2 = __half22float2(v0h[2]), p3 = __half22float2(v0h[3]);
        float2 r0 = __half22float2(v1h[0]), r1 = __half22float2(v1h[1]);
        float2 r2 = __half22float2(v1h[2]), r3 = __half22float2(v1h[3]);
        a0 = a0 * c + e0 * p0.x + e1 * r0.x;
        a1 = a1 * c + e0 * p0.y + e1 * r0.y;
        a2 = a2 * c + e0 * p1.x + e1 * r1.x;
        a3 = a3 * c + e0 * p1.y + e1 * r1.y;
        a4 = a4 * c + e0 * p2.x + e1 * r2.x;
        a5 = a5 * c + e0 * p2.y + e1 * r2.y;
        a6 = a6 * c + e0 * p3.x + e1 * r3.x;
        a7 = a7 * c + e0 * p3.y + e1 * r3.y;
    }
    if (e < end) {      // tail edge
        int s0 = esrc[e];
        uint4 ku0 = ((const uint4*)(kph + (size_t)s0 * 256))[lane];
        uint4 vu0 = ((const uint4*)(vph + (size_t)s0 * 256))[lane];
        float d0 = dot8h(q1, q2, ku0);
        #pragma unroll
        for (int o = G / 2; o > 0; o >>= 1)
            d0 += __shfl_xor_sync(0xffffffffu, d0, o);
        float l0 = d0 * pr;
        float mm = fmaxf(m, l0);
        float c  = expf(m - mm);
        float e0 = expf(l0 - mm);
        m = mm;
        denom = denom * c + e0;
        const __half2* v0h = (const __half2*)&vu0;
        float2 p0 = __half22float2(v0h[0]), p1 = __half22float2(v0h[1]);
        float2 p2 = __half22float2(v0h[2]), p3 = __half22float2(v0h[3]);
        a0 = a0 * c + e0 * p0.x; a1 = a1 * c + e0 * p0.y;
        a2 = a2 * c + e0 * p1.x; a3 = a3 * c + e0 * p1.y;
        a4 = a4 * c + e0 * p2.x; a5 = a5 * c + e0 * p2.y;
        a6 = a6 * c + e0 * p3.x; a7 = a7 * c + e0 * p3.y;
    }
    float invd = 1.0f / (denom + 1e-16f);
    float4* o4 = (float4*)(agg + (size_t)w * 256);
    o4[lane * 2]     = make_float4(a0 * invd, a1 * invd, a2 * invd, a3 * invd);
    o4[lane * 2 + 1] = make_float4(a4 * invd, a5 * invd, a6 * invd, a7 * invd);
}

// ---------------- fp16 GEMM: 128x128x32 tiles, m16n8k16 mma, double-buffered ----------------
// ACT: 0 = identity, 1 = gelu(A), 3 = BN+ReLU(A) via stats
// SKIP: 0 = none, 2 = blend with relu(bn(hres)) recomputed in epilogue
// PACKH: 1 = write fp16 k (cols<256) / v (cols>=512); fp32 store only q cols
// Layouts: A smem row-major fp16 [2][128][40] (stride 20 words: banks 20*gq+qc all-distinct);
//          B smem k-paired __half2 [2][16][136] (stride 136 words: 136%32=8 ->
//          fragment bank = 8*qc + gq, all 32 distinct -> conflict-free; the round-12
//          stride-128 layout had bank = n%32 independent of qc -> 4-way conflict = regression)
#define ASH(b,r,c) sA[(size_t)(b)*128*40 + (r)*40 + (c)]
#define BSH(b,kp,n) sB[(size_t)(b)*16*136 + (kp)*136 + (n)]
#define GEMM_SMEM (2*128*40*2 + 2*16*136*4)

template <int ACT, int SKIP, int PACKH>
__global__ __launch_bounds__(256)
void gemm_f16(const float* __restrict__ A, const float* __restrict__ B,
              const float* __restrict__ bias, float* __restrict__ C,
              int M, int K, int N, int lda, int ldb, int ldc,
              const float* __restrict__ skipv, const float* __restrict__ hres,
              const float* __restrict__ bnsum, const float* __restrict__ bnsq,
              const float* __restrict__ gamma, const float* __restrict__ beta,
              __half* __restrict__ kph, __half* __restrict__ vph) {
    extern __shared__ unsigned char smem_raw[];
    __half* sA = (__half*)smem_raw;                            // [2][128][40]
    unsigned* sB = (unsigned*)(smem_raw + 2 * 128 * 40 * 2);   // [2][16][136] half2

    const int bm = blockIdx.y * 128;
    const int bn = blockIdx.x * 128;
    const int tid = threadIdx.x;        // 256
    const int wid = tid >> 5, lane = tid & 31;
    const int wm = (wid >> 1) * 32;
    const int wn = (wid & 1) * 64;
    const int gq = lane >> 2;           // 0..7
    const int qc = lane & 3;            // 0..3

    // A loader: row = tid>>3 (+32*l), k-quad = (tid&7)*4
    const int arow = tid >> 3;
    const int akq  = (tid & 7) * 4;
    // B loader: k-pair = tid>>4 (0..15), n-quad = (tid&15)*4 (+64 second pass)
    const int bkp = tid >> 4;
    const int bn4 = (tid & 15) * 4;

    float acc[2][8][4] = {};
    const float4 z4 = make_float4(0.f, 0.f, 0.f, 0.f);

    // ---- prologue: load stage 0 ----
    #pragma unroll
    for (int l = 0; l < 4; l++) {
        int row = arow + l * 32;
        int gm = bm + row;
        float4 v = (gm < M) ? *(const float4*)(A + (size_t)gm * lda + akq) : z4;
        if (ACT == 1) {
            v.x = gelu_exact(v.x); v.y = gelu_exact(v.y);
            v.z = gelu_exact(v.z); v.w = gelu_exact(v.w);
        } else if (ACT == 3) {
            v.x = bn_relu(v.x, akq + 0, bnsum, bnsq, gamma, beta);
            v.y = bn_relu(v.y, akq + 1, bnsum, bnsq, gamma, beta);
            v.z = bn_relu(v.z, akq + 2, bnsum, bnsq, gamma, beta);
            v.w = bn_relu(v.w, akq + 3, bnsum, bnsq, gamma, beta);
        }
        *(uint2*)&ASH(0, row, akq) = make_uint2(pack_h2(v.x, v.y), pack_h2(v.z, v.w));
    }
    #pragma unroll
    for (int l = 0; l < 2; l++) {
        int n4 = bn4 + l * 64;
        float4 r0 = *(const float4*)(B + (size_t)(2 * bkp)     * ldb + bn + n4);
        float4 r1 = *(const float4*)(B + (size_t)(2 * bkp + 1) * ldb + bn + n4);
        *(uint4*)&BSH(0, bkp, n4) = make_uint4(pack_h2(r0.x, r1.x), pack_h2(r0.y, r1.y),
                                               pack_h2(r0.z, r1.z), pack_h2(r0.w, r1.w));
    }
    __syncthreads();

    for (int k0 = 0; k0 < K; k0 += 32) {
        const int cur = (k0 >> 5) & 1, nxt = cur ^ 1;
        const int kn = k0 + 32;
        const bool have_next = kn < K;

        // ---- issue next-stage LDGs ----
        float4 ra[4], rb0[2], rb1[2];
        if (have_next) {
            #pragma unroll
            for (int l = 0; l < 4; l++) {
                int gm = bm + arow + l * 32;
                ra[l] = (gm < M) ? *(const float4*)(A + (size_t)gm * lda + kn + akq) : z4;
            }
            #pragma unroll
            for (int l = 0; l < 2; l++) {
                int n4 = bn4 + l * 64;
                rb0[l] = *(const float4*)(B + (size_t)(kn + 2 * bkp)     * ldb + bn + n4);
                rb1[l] = *(const float4*)(B + (size_t)(kn + 2 * bkp + 1) * ldb + bn + n4);
            }
        }

        // ---- 2 k16 mma steps on current buffer ----
        #pragma unroll
        for (int kb = 0; kb < 32; kb += 16) {
            unsigned af[2][4];
            #pragma unroll
            for (int mt = 0; mt < 2; mt++) {
                int r = wm + mt * 16 + gq;
                af[mt][0] = *(const unsigned*)&ASH(cur, r,     kb + 2 * qc);
                af[mt][1] = *(const unsigned*)&ASH(cur, r + 8, kb + 2 * qc);
                af[mt][2] = *(const unsigned*)&ASH(cur, r,     kb + 2 * qc + 8);
                af[mt][3] = *(const unsigned*)&ASH(cur, r + 8, kb + 2 * qc + 8);
            }
            #pragma unroll
            for (int nt = 0; nt < 8; nt++) {
                int n = wn + nt * 8 + gq;
                unsigned bf[2];
                bf[0] = BSH(cur, (kb >> 1) + qc,     n);
                bf[1] = BSH(cur, (kb >> 1) + qc + 4, n);
                mma_f16(acc[0][nt], af[0], bf);
                mma_f16(acc[1][nt], af[1], bf);
            }
        }

        // ---- store next stage ----
        if (have_next) {
            #pragma unroll
            for (int l = 0; l < 4; l++) {
                float4 v = ra[l];
                if (ACT == 1) {
                    v.x = gelu_exact(v.x); v.y = gelu_exact(v.y);
                    v.z = gelu_exact(v.z); v.w = gelu_exact(v.w);
                } else if (ACT == 3) {
                    v.x = bn_relu(v.x, kn + akq + 0, bnsum, bnsq, gamma, beta);
                    v.y = bn_relu(v.y, kn + akq + 1, bnsum, bnsq, gamma, beta);
                    v.z = bn_relu(v.z, kn + akq + 2, bnsum, bnsq, gamma, beta);
                    v.w = bn_relu(v.w, kn + akq + 3, bnsum, bnsq, gamma, beta);
                }
                *(uint2*)&ASH(nxt, arow + l * 32, akq) =
                    make_uint2(pack_h2(v.x, v.y), pack_h2(v.z, v.w));
            }
            #pragma unroll
            for (int l = 0; l < 2; l++) {
                int n4 = bn4 + l * 64;
                *(uint4*)&BSH(nxt, bkp, n4) =
                    make_uint4(pack_h2(rb0[l].x, rb1[l].x), pack_h2(rb0[l].y, rb1[l].y),
                               pack_h2(rb0[l].z, rb1[l].z), pack_h2(rb0[l].w, rb1[l].w));
            }
        }
        __syncthreads();
    }

    // ---- epilogue (C fragment layout identical to m16n8k8) ----
    float s = 1.f, s1 = 0.f;
    if (SKIP == 2) {
        s = 1.0f / (1.0f + expf(-skipv[0]));
        s1 = 1.0f - s;
    }
    #pragma unroll
    for (int mt = 0; mt < 2; mt++) {
        #pragma unroll
        for (int half = 0; half < 2; half++) {
            int gm = bm + wm + mt * 16 + half * 8 + gq;
            if (gm >= M) continue;
            #pragma unroll
            for (int nt = 0; nt < 8; nt++) {
                int gn = bn + wn + nt * 8 + qc * 2;
                float v0 = acc[mt][nt][half * 2 + 0];
                float v1 = acc[mt][nt][half * 2 + 1];
                if (bias) { v0 += bias[gn]; v1 += bias[gn + 1]; }
                if (SKIP == 2) {
                    const float* hb = hres + (size_t)gm * ldc + gn;
                    float h0 = bn_relu(hb[0], gn,     bnsum, bnsq, gamma, beta);
                    float h1 = bn_relu(hb[1], gn + 1, bnsum, bnsq, gamma, beta);
                    v0 = s * v0 + s1 * h0;
                    v1 = s * v1 + s1 * h1;
                }
                if (PACKH) {
                    if (gn < 256) {
                        *(__half2*)(kph + (size_t)gm * 256 + gn) = __floats2half2_rn(v0, v1);
                    } else if (gn >= 512) {
                        *(__half2*)(vph + (size_t)gm * 256 + gn - 512) = __floats2half2_rn(v0, v1);
                    } else {
                        *(float2*)(C + (size_t)gm * ldc + gn) = make_float2(v0, v1);
                    }
                } else {
                    *(float2*)(C + (size_t)gm * ldc + gn) = make_float2(v0, v1);
                }
            }
        }
    }
}

// ---------------- BN stats ----------------
__global__ void bn_stats_kernel(const float* __restrict__ x, float* __restrict__ sum,
                                float* __restrict__ sumsq, int n) {
    int col = threadIdx.x;
    float s = 0.f, s2 = 0.f;
    for (int r = blockIdx.x; r < n; r += gridDim.x) {
        float v = x[(size_t)r * 256 + col];
        s += v; s2 += v * v;
    }
    atomicAdd(&sum[col], s);
    atomicAdd(&sumsq[col], s2);
}

// ---------------- host orchestration ----------------
extern "C" void kernel_launch(void* const* d_in, const int* in_sizes, int n_in,
                              void* d_out, int out_size) {
    const float* x       = (const float*)d_in[0];
    const int*   ei      = (const int*)  d_in[1];
    const float* w_kqv1  = (const float*)d_in[2];
    const float* b_kqv1  = (const float*)d_in[3];
    const float* k_rel1  = (const float*)d_in[4];
    const float* v_rel1  = (const float*)d_in[5];
    const float* p_rel1  = (const float*)d_in[6];
    const float* w_out1  = (const float*)d_in[7];
    const float* b_out1  = (const float*)d_in[8];
    const float* bn_gamma = (const float*)d_in[10];
    const float* bn_beta  = (const float*)d_in[11];
    const float* w_kqv2  = (const float*)d_in[12];
    const float* b_kqv2  = (const float*)d_in[13];
    const float* k_rel2  = (const float*)d_in[14];
    const float* v_rel2  = (const float*)d_in[15];
    const float* p_rel2  = (const float*)d_in[16];
    const float* w_out2  = (const float*)d_in[17];
    const float* b_out2  = (const float*)d_in[18];
    const float* skip2   = (const float*)d_in[19];

    const int* src = ei;
    const int* dst = ei + N_EDGES;
    float* outp = (float*)d_out;

    float *kqv, *agg, *tmp, *bnsum, *bnsq;
    float *w1p, *b1p, *w2p, *b2p;
    __half *kph, *vph;
    int *count, *off, *cursor, *esrc;
    cudaGetSymbolAddress((void**)&kqv,    g_kqv);
    cudaGetSymbolAddress((void**)&kph,    g_kph);
    cudaGetSymbolAddress((void**)&vph,    g_vph);
    cudaGetSymbolAddress((void**)&agg,    g_agg);
    cudaGetSymbolAddress((void**)&tmp,    g_tmp);
    cudaGetSymbolAddress((void**)&bnsum,  g_bnsum);
    cudaGetSymbolAddress((void**)&bnsq,   g_bnsq);
    cudaGetSymbolAddress((void**)&w1p,    g_w1p);
    cudaGetSymbolAddress((void**)&b1p,    g_b1p);
    cudaGetSymbolAddress((void**)&w2p,    g_w2p);
    cudaGetSymbolAddress((void**)&b2p,    g_b2p);
    cudaGetSymbolAddress((void**)&count,  g_count);
    cudaGetSymbolAddress((void**)&off,    g_off);
    cudaGetSymbolAddress((void**)&cursor, g_cursor);
    cudaGetSymbolAddress((void**)&esrc,   g_esrc);

    cudaFuncSetAttribute(gemm_f16<0,0,1>, cudaFuncAttributeMaxDynamicSharedMemorySize, GEMM_SMEM);
    cudaFuncSetAttribute(gemm_f16<3,0,1>, cudaFuncAttributeMaxDynamicSharedMemorySize, GEMM_SMEM);
    cudaFuncSetAttribute(gemm_f16<1,0,0>, cudaFuncAttributeMaxDynamicSharedMemorySize, GEMM_SMEM);
    cudaFuncSetAttribute(gemm_f16<1,2,0>, cudaFuncAttributeMaxDynamicSharedMemorySize, GEMM_SMEM);

    const int MT128 = (N_NODES + 127) / 128;   // 235
    const int ATTN_BLOCKS = (N_NODES + 7) / 8;

    // ---- weight prep ----
    combine_kernel<<<((512 + 1) * 768 + 255) / 256, 256>>>(w_kqv1, b_kqv1, k_rel1, v_rel1,
                                                           w1p, b1p, 512, 64);
    combine_kernel<<<((256 + 1) * 768 + 255) / 256, 256>>>(w_kqv2, b_kqv2, k_rel2, v_rel2,
                                                           w2p, b2p, 256, 256);

    // ---- CSR build ----
    zero_init_kernel<<<(N_NODES + 255) / 256, 256>>>(count, bnsum, bnsq);
    hist_kernel<<<(N_EDGES + 255) / 256, 256>>>(dst, count);
    scan_kernel<<<1, 1024>>>(count, off, cursor);
    scatter_kernel<<<(N_EDGES + 255) / 256, 256>>>(src, dst, cursor, esrc);

    // ================= Layer 1 (heads=4, d=64) =================
    gemm_f16<0,0,1><<<dim3(768 / 128, MT128), 256, GEMM_SMEM>>>(x, w1p, b1p, kqv,
        N_NODES, 512, 768, 512, 768, 768, nullptr, nullptr,
        nullptr, nullptr, nullptr, nullptr, kph, vph);
    attn_kernel<4><<<ATTN_BLOCKS, 256>>>(kqv + 256, kph, vph, off, esrc, p_rel1,
                                         agg, 0.125f);
    gemm_f16<1,0,0><<<dim3(256 / 128, MT128), 256, GEMM_SMEM>>>(agg, w_out1, b_out1, tmp,
        N_NODES, 256, 256, 256, 256, 256, nullptr, nullptr,
        nullptr, nullptr, nullptr, nullptr, nullptr, nullptr);
    bn_stats_kernel<<<256, 256>>>(tmp, bnsum, bnsq, N_NODES);

    // ================= Layer 2 (heads=1, d=256) =================
    gemm_f16<3,0,1><<<dim3(768 / 128, MT128), 256, GEMM_SMEM>>>(tmp, w2p, b2p, kqv,
        N_NODES, 256, 768, 256, 768, 768, nullptr, nullptr,
        bnsum, bnsq, bn_gamma, bn_beta, kph, vph);
    attn_kernel<1><<<ATTN_BLOCKS, 256>>>(kqv + 256, kph, vph, off, esrc, p_rel2,
                                         agg, 0.0625f);
    gemm_f16<1,2,0><<<dim3(256 / 128, MT128), 256, GEMM_SMEM>>>(agg, w_out2, b_out2, outp,
        N_NODES, 256, 256, 256, 256, 256, skip2, tmp,
        bnsum, bnsq, bn_gamma, bn_beta, nullptr, nullptr);

    (void)in_sizes; (void)n_in; (void)out_size;
}